// round 16
// baseline (speedup 1.0000x reference)
#include <cuda_runtime.h>
#include <cstdint>
#include <cstddef>

#define NCN    32      // 2*16 centroid matrices
#define NB     1024    // number of sampled indices
#define NBINS  2048    // batch size B (histogram bins)
#define NCHUNK 256     // b-chunks in main kernel grid (4 tasks each)
#define TPB    4       // tasks (warp pairs) per block
#define NMID   8       // mid-reduced chunk count
#define ST     36      // padded row stride for final-kernel matrices

// single-node minimax rational log on spectrum [1/3, 3]:
//   log(M) ~= ALPHA * (M - I)(M + I)^{-1} = ALPHA*I - ALPHA*((M+I)/2)^{-1}
#define ALPHA  2.146f

#define NSQ    4       // Newton-Schulz sqrt iterations

// ---- scratch (static device globals; no allocation APIs) ----
__device__ float g_partial[NCHUNK * NCN * 1024];      // per-chunk partial sums
__device__ float g_partial2[NMID * NCN * 1024];       // mid-reduced partials
__device__ int   g_list[NB];                          // distinct xb values (ascending)
__device__ float g_cnt[NB];                           // multiplicity weights (0 = idle)

// ---- packed f32x2 helpers ----
union f2u { float2 f; unsigned long long u; };
__device__ __forceinline__ float2 ffma2(float2 a, float2 b, float2 c) {
    f2u A, B, C, R; A.f = a; B.f = b; C.f = c;
    asm("fma.rn.f32x2 %0, %1, %2, %3;" : "=l"(R.u) : "l"(A.u), "l"(B.u), "l"(C.u));
    return R.f;
}
struct __align__(16) pf4 { float2 lo, hi; };

__device__ __forceinline__ float f4c(const float4 v, int c) {
    return c == 0 ? v.x : c == 1 ? v.y : c == 2 ? v.z : v.w;
}

#define PAIR_BAR(id) asm volatile("bar.sync %0, %1;" :: "r"(id), "r"(64) : "memory")

// ============================================================================
// Dedup: smem histogram + 3-barrier shfl-based compaction scan (deterministic).
// ============================================================================
__global__ void dedup_kernel(const int* __restrict__ idx) {
    __shared__ int h[NBINS];
    __shared__ int wsum[32];
    const int t = threadIdx.x;
    const int lane = t & 31, wid = t >> 5;
    h[t] = 0; h[t + 1024] = 0;
    g_list[t] = 0; g_cnt[t] = 0.f;
    __syncthreads();
    atomicAdd(&h[idx[t]], 1);
    __syncthreads();
    const int h0 = h[2 * t], h1 = h[2 * t + 1];
    const int p0 = h0 > 0, p1 = h1 > 0;
    int v = p0 + p1;
    #pragma unroll
    for (int o = 1; o < 32; o <<= 1) {
        int n = __shfl_up_sync(0xffffffffu, v, o);
        if (lane >= o) v += n;
    }
    if (lane == 31) wsum[wid] = v;
    __syncthreads();
    if (wid == 0) {
        int s = wsum[lane];
        #pragma unroll
        for (int o = 1; o < 32; o <<= 1) {
            int n = __shfl_up_sync(0xffffffffu, s, o);
            if (lane >= o) s += n;
        }
        wsum[lane] = s;
    }
    __syncthreads();
    const int excl = v - (p0 + p1) + (wid ? wsum[wid - 1] : 0);
    if (p0) { g_list[excl] = 2 * t;          g_cnt[excl] = (float)h0; }
    if (p1) { g_list[excl + p0] = 2 * t + 1; g_cnt[excl + p0] = (float)h1; }
}
__global__ void nodedup_kernel(const int* __restrict__ idx) {
    g_list[threadIdx.x] = idx[threadIdx.x];
    g_cnt[threadIdx.x] = 1.f;
}

// ============================================================================
// Main kernel: accumulate w*ALPHA*inv(B), B = 0.5*(X + C).
// 64 threads (a warp PAIR) per inverse: thread owns half a row (16 cols),
// B2 = 16 regs -> fits 64-reg budget -> 4 blocks/SM = 32 warps/SM.
// Block-pivot (4x4) GJ, 8 rounds. Per round: both halves store panel halves;
// the half owning the block columns runs the in-register LU solve and
// publishes F (float4/row) via smem; all 64 threads apply the rank-4 update
// to their half. Named pair barriers (64 threads).
// ============================================================================
__global__ void __launch_bounds__(256, 4) main_kernel(const float* __restrict__ X,
                                                      const float* __restrict__ Cin) {
    __shared__ __align__(16) float sC[32 * 36];          // C rows (stride 36)
    __shared__ __align__(16) float sBuf[TPB][32 * 36];   // per-task accumulator
    __shared__ __align__(16) float sBc[TPB][2][4 * 36];  // dbl-buffered 4-row panel
    __shared__ __align__(16) float4 sF[TPB][32];         // per-row F broadcast
    const int tid = threadIdx.x, warp = tid >> 5, lane = tid & 31;
    const int pair = warp >> 1, half = warp & 1;
    const int cn = blockIdx.y;
    const int slot = blockIdx.x * TPB + pair;
    const int barid = pair + 1;

    for (int k = tid; k < 1024; k += 256)
        sC[(k >> 5) * 36 + (k & 31)] = Cin[cn * 1024 + k];
    __syncthreads();

    const float w = g_cnt[slot];
    // branchless: idle slots (w==0) compute on g_list=0 (valid SPD), weight 0.
    const float* Xrow = X + (((size_t)g_list[slot] * NCN + cn) << 10)
                        + (lane << 5) + (half << 4);
    const pf4* crow = (const pf4*)(sC + lane * 36 + half * 16);
    const float2 h2 = make_float2(0.5f, 0.5f);

    // B half-row: 16 columns in 8 float2 regs
    float2 B2[8];
    #pragma unroll
    for (int q = 0; q < 4; q++) {
        const float4 xv = ((const float4*)Xrow)[q];
        const pf4 cv = crow[q];
        B2[2*q]   = ffma2(h2, make_float2(xv.x, xv.y),
                          make_float2(0.5f * cv.lo.x, 0.5f * cv.lo.y));
        B2[2*q+1] = ffma2(h2, make_float2(xv.z, xv.w),
                          make_float2(0.5f * cv.hi.x, 0.5f * cv.hi.y));
    }

    const int myblk = lane >> 2, myr = lane & 3;

    #pragma unroll
    for (int kb = 0; kb < 8; kb++) {
        float* bc = sBc[pair][kb & 1];
        // owner rows store their half of the 4-row panel
        if (myblk == kb) {
            pf4* bp = (pf4*)(bc + myr * 36 + half * 16);
            #pragma unroll
            for (int q = 0; q < 4; q++) {
                pf4 v; v.lo = B2[2*q]; v.hi = B2[2*q+1];
                bp[q] = v;
            }
        }
        PAIR_BAR(barid);

        const int hstar = kb >> 2;       // half that owns block columns
        if (half == hstar) {
            // pivot block P (panel rows 0..3, global cols 4kb..4kb+3)
            const float4 p0 = *(const float4*)(bc +   0 + 4 * kb);
            const float4 p1 = *(const float4*)(bc +  36 + 4 * kb);
            const float4 p2 = *(const float4*)(bc +  72 + 4 * kb);
            const float4 p3 = *(const float4*)(bc + 108 + 4 * kb);
            const int lq = kb & 3;       // local pf4 index of block columns
            const float cd0 = B2[2*lq].x   - ((lane == 4*kb + 0) ? 1.f : 0.f);
            const float cd1 = B2[2*lq].y   - ((lane == 4*kb + 1) ? 1.f : 0.f);
            const float cd2 = B2[2*lq+1].x - ((lane == 4*kb + 2) ? 1.f : 0.f);
            const float cd3 = B2[2*lq+1].y - ((lane == 4*kb + 3) ? 1.f : 0.f);

            // F * P = cd  <=>  P^T F^T = cd^T; no-pivot LU of M = P^T (P SPD)
            float m01 = p1.x, m02 = p2.x, m03 = p3.x;
            float m11 = p1.y, m12 = p2.y, m13 = p3.y;
            float m21 = p1.z, m22 = p2.z, m23 = p3.z;
            float m31 = p1.w, m32 = p2.w, m33 = p3.w;
            const float i00 = __fdividef(1.f, p0.x);
            const float l10 = p0.y * i00, l20 = p0.z * i00, l30 = p0.w * i00;
            m11 = fmaf(-l10, m01, m11); m12 = fmaf(-l10, m02, m12); m13 = fmaf(-l10, m03, m13);
            m21 = fmaf(-l20, m01, m21); m22 = fmaf(-l20, m02, m22); m23 = fmaf(-l20, m03, m23);
            m31 = fmaf(-l30, m01, m31); m32 = fmaf(-l30, m02, m32); m33 = fmaf(-l30, m03, m33);
            const float i11 = __fdividef(1.f, m11);
            const float l21 = m21 * i11, l31 = m31 * i11;
            m22 = fmaf(-l21, m12, m22); m23 = fmaf(-l21, m13, m23);
            m32 = fmaf(-l31, m12, m32); m33 = fmaf(-l31, m13, m33);
            const float i22 = __fdividef(1.f, m22);
            const float l32 = m32 * i22;
            m33 = fmaf(-l32, m23, m33);
            const float i33 = __fdividef(1.f, m33);
            const float y0 = cd0;
            const float y1 = fmaf(-l10, y0, cd1);
            const float y2 = fmaf(-l21, y1, fmaf(-l20, y0, cd2));
            const float y3 = fmaf(-l32, y2, fmaf(-l31, y1, fmaf(-l30, y0, cd3)));
            const float F3 = y3 * i33;
            const float F2 = fmaf(-m23, F3, y2) * i22;
            const float F1 = fmaf(-m13, F3, fmaf(-m12, F2, y1)) * i11;
            const float F0 = fmaf(-m03, F3, fmaf(-m02, F2, fmaf(-m01, F1, y0))) * i00;
            sF[pair][lane] = make_float4(F0, F1, F2, F3);
        }
        PAIR_BAR(barid);

        const float4 Fv = sF[pair][lane];
        // rank-4 update of own half against panel half
        {
            const float2 n0 = make_float2(-Fv.x, -Fv.x);
            const float2 n1 = make_float2(-Fv.y, -Fv.y);
            const float2 n2 = make_float2(-Fv.z, -Fv.z);
            const float2 n3 = make_float2(-Fv.w, -Fv.w);
            const pf4* r0 = (const pf4*)(bc +   0 + half * 16);
            const pf4* r1 = (const pf4*)(bc +  36 + half * 16);
            const pf4* r2 = (const pf4*)(bc +  72 + half * 16);
            const pf4* r3 = (const pf4*)(bc + 108 + half * 16);
            #pragma unroll
            for (int q = 0; q < 4; q++) {
                const pf4 v0 = r0[q], v1 = r1[q], v2 = r2[q], v3 = r3[q];
                B2[2*q]   = ffma2(n0, v0.lo, ffma2(n1, v1.lo,
                            ffma2(n2, v2.lo, ffma2(n3, v3.lo, B2[2*q]))));
                B2[2*q+1] = ffma2(n0, v0.hi, ffma2(n1, v1.hi,
                            ffma2(n2, v2.hi, ffma2(n3, v3.hi, B2[2*q+1]))));
            }
        }
        // block-column fixup (only the half that owns them)
        if (half == (kb >> 2)) {
            const int lq = kb & 3;
            B2[2*lq]   = make_float2(((lane == 4*kb + 0) ? 1.f : 0.f) - Fv.x,
                                     ((lane == 4*kb + 1) ? 1.f : 0.f) - Fv.y);
            B2[2*lq+1] = make_float2(((lane == 4*kb + 2) ? 1.f : 0.f) - Fv.z,
                                     ((lane == 4*kb + 3) ? 1.f : 0.f) - Fv.w);
        }
    }

    // store w*ALPHA * (own half of Binv) into task accumulator
    {
        const float sw = w * ALPHA;
        pf4* br = (pf4*)(sBuf[pair] + lane * 36 + half * 16);
        #pragma unroll
        for (int q = 0; q < 4; q++) {
            pf4 v;
            v.lo = make_float2(sw * B2[2*q].x, sw * B2[2*q].y);
            v.hi = make_float2(sw * B2[2*q+1].x, sw * B2[2*q+1].y);
            br[q] = v;
        }
    }
    __syncthreads();

    // deterministic block reduction over the 4 tasks -> partial buffer
    float* outp = g_partial + ((size_t)blockIdx.x * NCN + cn) * 1024;
    for (int e = tid; e < 1024; e += 256) {
        const int r = e >> 5, cc = e & 31;
        float s = 0.f;
        #pragma unroll
        for (int tp = 0; tp < TPB; tp++) s += sBuf[tp][r * 36 + cc];
        outp[e] = s;
    }
}

// ============================================================================
// Mid-reduction: collapse 256 chunks -> 8, at full-chip DRAM bandwidth.
// ============================================================================
__global__ void midreduce_kernel() {
    const int cn = blockIdx.x, g = blockIdx.y, tid = threadIdx.x;
    float s = 0.f;
    const float* pp = g_partial + ((size_t)(g * (NCHUNK / NMID)) * NCN + cn) * 1024 + tid;
    #pragma unroll
    for (int c = 0; c < NCHUNK / NMID; c++) s += pp[(size_t)c * NCN * 1024];
    g_partial2[((size_t)g * NCN + cn) * 1024 + tid] = s;
}

// ============================================================================
// Final kernel: 256 threads, register-tiled matmul passes.
//   Cp = sqrtm(C) (NS);  G = eta*(Cp*Abar*Cp - ALPHA*I)   [= -L, PSD]
//   sgn(L) = -I analytically (matrix Jensen), E = -expm(G) ~= -(I + G + G^2/2)
//   out = Cp * E * Cp
// ============================================================================
__device__ __forceinline__ void mm32(const float* __restrict__ A,
                                     const float* __restrict__ B,
                                     float* acc, int r0, int j) {
    #pragma unroll
    for (int kb = 0; kb < 8; kb++) {
        const float4 a0 = *(const float4*)(A + (r0+0)*ST + 4*kb);
        const float4 a1 = *(const float4*)(A + (r0+1)*ST + 4*kb);
        const float4 a2 = *(const float4*)(A + (r0+2)*ST + 4*kb);
        const float4 a3 = *(const float4*)(A + (r0+3)*ST + 4*kb);
        #pragma unroll
        for (int t = 0; t < 4; t++) {
            const float bk = B[(4*kb + t)*ST + j];
            acc[0] = fmaf(f4c(a0, t), bk, acc[0]);
            acc[1] = fmaf(f4c(a1, t), bk, acc[1]);
            acc[2] = fmaf(f4c(a2, t), bk, acc[2]);
            acc[3] = fmaf(f4c(a3, t), bk, acc[3]);
        }
    }
}

__global__ void __launch_bounds__(256) final_kernel(const float* __restrict__ C,
                                                    float* __restrict__ out) {
    __shared__ __align__(16) float sCp[32*ST];
    __shared__ __align__(16) float b1[32*ST], b2[32*ST], b3[32*ST], b4[32*ST], b5[32*ST];
    __shared__ float sRed[8];
    __shared__ float sScal;
    const int cn = blockIdx.x, tid = threadIdx.x;
    const int warp = tid >> 5, j = tid & 31, r0 = warp << 2;

    // load C rows; trace
    float cv[4];
    #pragma unroll
    for (int r = 0; r < 4; r++) cv[r] = C[cn * 1024 + (r0 + r) * 32 + j];
    {
        float v = 0.f;
        #pragma unroll
        for (int r = 0; r < 4; r++) if (j == r0 + r) v += cv[r];
        #pragma unroll
        for (int o = 16; o > 0; o >>= 1) v += __shfl_xor_sync(0xffffffffu, v, o);
        if (j == 0) sRed[warp] = v;
    }
    __syncthreads();
    if (tid == 0) {
        float s = 0.f;
        #pragma unroll
        for (int r = 0; r < 8; r++) s += sRed[r];
        sScal = s * (1.f / 32.f);
    }
    __syncthreads();
    const float c = sScal, invc = 1.f / c;

    // NS coupled sqrt on C/c: Y in b1, Z in b2
    #pragma unroll
    for (int r = 0; r < 4; r++) {
        b1[(r0 + r) * ST + j] = cv[r] * invc;
        b2[(r0 + r) * ST + j] = (r0 + r == j) ? 1.f : 0.f;
    }
    __syncthreads();
    float *Y = b1, *Z = b2, *Pm = b3, *Ya = b4, *Za = b5;
    for (int it = 0; it < NSQ; it++) {
        float acc[4] = {0.f, 0.f, 0.f, 0.f};
        mm32(Z, Y, acc, r0, j);
        #pragma unroll
        for (int r = 0; r < 4; r++)
            Pm[(r0 + r) * ST + j] = ((r0 + r == j) ? 1.5f : 0.f) - 0.5f * acc[r];
        __syncthreads();
        float a1[4] = {0.f, 0.f, 0.f, 0.f}, a2[4] = {0.f, 0.f, 0.f, 0.f};
        mm32(Y, Pm, a1, r0, j);
        mm32(Pm, Z, a2, r0, j);
        #pragma unroll
        for (int r = 0; r < 4; r++) {
            Ya[(r0 + r) * ST + j] = a1[r];
            Za[(r0 + r) * ST + j] = a2[r];
        }
        __syncthreads();
        float* t1 = Y; float* t2 = Z;
        Y = Ya; Z = Za; Ya = t1; Za = t2;
    }
    // Cp = Y * sqrt(c)
    const float sc = sqrtf(c);
    #pragma unroll
    for (int r = 0; r < 4; r++) sCp[(r0 + r) * ST + j] = Y[(r0 + r) * ST + j] * sc;
    __syncthreads();
    float *Ta = b1, *Tb = b2, *G = b3, *P2 = b4, *E = b5;

    // Abar -> Ta
    #pragma unroll
    for (int r = 0; r < 4; r++) {
        float s = 0.f;
        #pragma unroll
        for (int g = 0; g < NMID; g++)
            s += g_partial2[((size_t)g * NCN + cn) * 1024 + (r0 + r) * 32 + j];
        Ta[(r0 + r) * ST + j] = s * (1.f / 1024.f);
    }
    __syncthreads();
    // U = Abar * Cp -> Tb
    {
        float acc[4] = {0.f, 0.f, 0.f, 0.f};
        mm32(Ta, sCp, acc, r0, j);
        #pragma unroll
        for (int r = 0; r < 4; r++) Tb[(r0 + r) * ST + j] = acc[r];
    }
    __syncthreads();
    // G = eta*(Cp*U - ALPHA*I)
    {
        float acc[4] = {0.f, 0.f, 0.f, 0.f};
        mm32(sCp, Tb, acc, r0, j);
        #pragma unroll
        for (int r = 0; r < 4; r++)
            G[(r0 + r) * ST + j] = 0.01f * (acc[r] - ((r0 + r == j) ? ALPHA : 0.f));
    }
    __syncthreads();
    // P2 = G*G
    {
        float acc[4] = {0.f, 0.f, 0.f, 0.f};
        mm32(G, G, acc, r0, j);
        #pragma unroll
        for (int r = 0; r < 4; r++) P2[(r0 + r) * ST + j] = acc[r];
    }
    __syncthreads();
    // E = -(I + G + P2/2)
    #pragma unroll
    for (int r = 0; r < 4; r++)
        E[(r0 + r) * ST + j] = -(((r0 + r == j) ? 1.f : 0.f)
                                 + G[(r0 + r) * ST + j]
                                 + 0.5f * P2[(r0 + r) * ST + j]);
    __syncthreads();
    // V = E * Cp -> Ta
    {
        float acc[4] = {0.f, 0.f, 0.f, 0.f};
        mm32(E, sCp, acc, r0, j);
        #pragma unroll
        for (int r = 0; r < 4; r++) Ta[(r0 + r) * ST + j] = acc[r];
    }
    __syncthreads();
    // out = Cp * V
    {
        float acc[4] = {0.f, 0.f, 0.f, 0.f};
        mm32(sCp, Ta, acc, r0, j);
        #pragma unroll
        for (int r = 0; r < 4; r++) out[cn * 1024 + (r0 + r) * 32 + j] = acc[r];
    }
}

// ============================================================================
extern "C" void kernel_launch(void* const* d_in, const int* in_sizes, int n_in,
                              void* d_out, int out_size) {
    const float* X = nullptr;
    const float* C = nullptr;
    const int* idx = nullptr;
    int xElems = 0;
    for (int i = 0; i < n_in; i++) {
        if (in_sizes[i] == NB) idx = (const int*)d_in[i];
        else if (in_sizes[i] == NCN * 1024) C = (const float*)d_in[i];
        else { X = (const float*)d_in[i]; xElems = in_sizes[i]; }
    }
    const int batch = xElems / (NCN * 1024);

    if (batch == NBINS) {
        dedup_kernel<<<1, 1024>>>(idx);
    } else {
        nodedup_kernel<<<1, NB>>>(idx);
    }
    dim3 grid(NCHUNK, NCN);
    main_kernel<<<grid, 256>>>(X, C);
    dim3 mgrid(NCN, NMID);
    midreduce_kernel<<<mgrid, 1024>>>();
    final_kernel<<<NCN, 256>>>(C, (float*)d_out);
}

// round 17
// speedup vs baseline: 1.5227x; 1.5227x over previous
#include <cuda_runtime.h>
#include <cstdint>
#include <cstddef>

#define NCN    32      // 2*16 centroid matrices
#define NB     1024    // number of sampled indices
#define NBINS  2048    // batch size B (histogram bins)
#define NCHUNK 128     // b-chunks in main kernel grid
#define WPB    8       // warps per block (main kernel)
#define NMID   8       // mid-reduced chunk count
#define ST     36      // padded row stride for final-kernel matrices

// single-node minimax rational log on spectrum [1/3, 3]:
//   log(M) ~= ALPHA * (M - I)(M + I)^{-1} = ALPHA*I - ALPHA*((M+I)/2)^{-1}
#define ALPHA  2.146f
#define ETA    0.01f

// out = -(C0*C + C1*C*Abar*C + C2*C*Abar*C*Abar*C)   [Cp cancels: Cp*Cp = C]
#define CF0  (1.0f - ETA * ALPHA + 0.5f * ETA * ETA * ALPHA * ALPHA)
#define CF1  (ETA - ETA * ETA * ALPHA)
#define CF2  (0.5f * ETA * ETA)

// ---- scratch (static device globals; no allocation APIs) ----
__device__ float g_partial[NCHUNK * NCN * 1024];      // per-chunk partial sums
__device__ float g_partial2[NMID * NCN * 1024];       // mid-reduced partials
__device__ int   g_list[NB];                          // distinct xb values (ascending)
__device__ float g_cnt[NB];                           // multiplicity weights (0 = idle)

// ---- packed f32x2 helpers ----
union f2u { float2 f; unsigned long long u; };
__device__ __forceinline__ float2 ffma2(float2 a, float2 b, float2 c) {
    f2u A, B, C, R; A.f = a; B.f = b; C.f = c;
    asm("fma.rn.f32x2 %0, %1, %2, %3;" : "=l"(R.u) : "l"(A.u), "l"(B.u), "l"(C.u));
    return R.f;
}
struct __align__(16) pf4 { float2 lo, hi; };

__device__ __forceinline__ float f4c(const float4 v, int c) {
    return c == 0 ? v.x : c == 1 ? v.y : c == 2 ? v.z : v.w;
}

// ============================================================================
// Dedup: smem histogram + 3-barrier shfl-based compaction scan (deterministic).
// ============================================================================
__global__ void dedup_kernel(const int* __restrict__ idx) {
    __shared__ int h[NBINS];
    __shared__ int wsum[32];
    const int t = threadIdx.x;
    const int lane = t & 31, wid = t >> 5;
    h[t] = 0; h[t + 1024] = 0;
    g_list[t] = 0; g_cnt[t] = 0.f;
    __syncthreads();
    atomicAdd(&h[idx[t]], 1);
    __syncthreads();
    const int h0 = h[2 * t], h1 = h[2 * t + 1];
    const int p0 = h0 > 0, p1 = h1 > 0;
    int v = p0 + p1;
    #pragma unroll
    for (int o = 1; o < 32; o <<= 1) {
        int n = __shfl_up_sync(0xffffffffu, v, o);
        if (lane >= o) v += n;
    }
    if (lane == 31) wsum[wid] = v;
    __syncthreads();
    if (wid == 0) {
        int s = wsum[lane];
        #pragma unroll
        for (int o = 1; o < 32; o <<= 1) {
            int n = __shfl_up_sync(0xffffffffu, s, o);
            if (lane >= o) s += n;
        }
        wsum[lane] = s;
    }
    __syncthreads();
    const int excl = v - (p0 + p1) + (wid ? wsum[wid - 1] : 0);
    if (p0) { g_list[excl] = 2 * t;          g_cnt[excl] = (float)h0; }
    if (p1) { g_list[excl + p0] = 2 * t + 1; g_cnt[excl + p0] = (float)h1; }
}
__global__ void nodedup_kernel(const int* __restrict__ idx) {
    g_list[threadIdx.x] = idx[threadIdx.x];
    g_cnt[threadIdx.x] = 1.f;
}

// ============================================================================
// Main kernel (R13 proven config): accumulate w*ALPHA*inv(B), B = 0.5*(X + C).
// One warp per (slot, cn). Block-pivot (4x4) pivot-free Gauss-Jordan: 8
// rounds; per-round the lane solves F = cd * P^{-1} via in-register no-pivot
// LU of P^T (P SPD), then a rank-4 packed-FMA update. (256,3): no spills.
// ============================================================================
__global__ void __launch_bounds__(256, 3) main_kernel(const float* __restrict__ X,
                                                      const float* __restrict__ Cin) {
    __shared__ __align__(16) float sC[32 * 36];         // C rows (stride 36)
    __shared__ __align__(16) float sBuf[WPB][32 * 36];  // per-warp accumulator
    __shared__ __align__(16) float sBc[WPB][2][4 * 36]; // dbl-buffered 4-row panel
    const int tid = threadIdx.x, warp = tid >> 5, lane = tid & 31;
    const int cn = blockIdx.y;
    const int slot = blockIdx.x * WPB + warp;

    for (int k = tid; k < 1024; k += 256)
        sC[(k >> 5) * 36 + (k & 31)] = Cin[cn * 1024 + k];
    __syncthreads();

    float* bufrow = sBuf[warp] + lane * 36;
    pf4* br = (pf4*)bufrow;
    const float w = g_cnt[slot];

    if (w > 0.f) {
        const float* Xrow = X + (((size_t)g_list[slot] * NCN + cn) << 10) + (lane << 5);
        const pf4* crow = (const pf4*)(sC + lane * 36);
        const int myblk = lane >> 2, myr = lane & 3;
        const float2 h2 = make_float2(0.5f, 0.5f);

        // B = 0.5*(X + C)   (row `lane` in registers)
        float2 B2[16];
        #pragma unroll
        for (int q = 0; q < 8; q++) {
            const float4 xv = ((const float4*)Xrow)[q];
            const pf4 cv = crow[q];
            B2[2*q]   = ffma2(h2, make_float2(xv.x, xv.y),
                              make_float2(0.5f * cv.lo.x, 0.5f * cv.lo.y));
            B2[2*q+1] = ffma2(h2, make_float2(xv.z, xv.w),
                              make_float2(0.5f * cv.hi.x, 0.5f * cv.hi.y));
        }

        // block-pivot Gauss-Jordan inverse (8 rounds of 4 columns)
        #pragma unroll
        for (int kb = 0; kb < 8; kb++) {
            float* bc = sBc[warp][kb & 1];
            if (myblk == kb) {
                pf4* bp = (pf4*)(bc + myr * 36);
                #pragma unroll
                for (int q = 0; q < 8; q++) {
                    pf4 v; v.lo = B2[2*q]; v.hi = B2[2*q+1];
                    bp[q] = v;
                }
            }
            __syncwarp();
            // pivot block P (rows 0..3 of panel, cols 4kb..4kb+3)
            const float4 p0 = *(const float4*)(bc +   0 + 4 * kb);
            const float4 p1 = *(const float4*)(bc +  36 + 4 * kb);
            const float4 p2 = *(const float4*)(bc +  72 + 4 * kb);
            const float4 p3 = *(const float4*)(bc + 108 + 4 * kb);

            // own block-column values minus identity (unified owner trick)
            const float cd0 = B2[2*kb].x   - ((lane == 4*kb + 0) ? 1.f : 0.f);
            const float cd1 = B2[2*kb].y   - ((lane == 4*kb + 1) ? 1.f : 0.f);
            const float cd2 = B2[2*kb+1].x - ((lane == 4*kb + 2) ? 1.f : 0.f);
            const float cd3 = B2[2*kb+1].y - ((lane == 4*kb + 3) ? 1.f : 0.f);

            // Solve F * P = cd  <=>  P^T F^T = cd^T. LU of M = P^T (SPD: no pivot).
            float m01 = p1.x, m02 = p2.x, m03 = p3.x;
            float m11 = p1.y, m12 = p2.y, m13 = p3.y;
            float m21 = p1.z, m22 = p2.z, m23 = p3.z;
            float m31 = p1.w, m32 = p2.w, m33 = p3.w;
            const float i00 = __fdividef(1.f, p0.x);
            const float l10 = p0.y * i00, l20 = p0.z * i00, l30 = p0.w * i00;
            m11 = fmaf(-l10, m01, m11); m12 = fmaf(-l10, m02, m12); m13 = fmaf(-l10, m03, m13);
            m21 = fmaf(-l20, m01, m21); m22 = fmaf(-l20, m02, m22); m23 = fmaf(-l20, m03, m23);
            m31 = fmaf(-l30, m01, m31); m32 = fmaf(-l30, m02, m32); m33 = fmaf(-l30, m03, m33);
            const float i11 = __fdividef(1.f, m11);
            const float l21 = m21 * i11, l31 = m31 * i11;
            m22 = fmaf(-l21, m12, m22); m23 = fmaf(-l21, m13, m23);
            m32 = fmaf(-l31, m12, m32); m33 = fmaf(-l31, m13, m33);
            const float i22 = __fdividef(1.f, m22);
            const float l32 = m32 * i22;
            m33 = fmaf(-l32, m23, m33);
            const float i33 = __fdividef(1.f, m33);
            // forward substitution (unit lower)
            const float y0 = cd0;
            const float y1 = fmaf(-l10, y0, cd1);
            const float y2 = fmaf(-l21, y1, fmaf(-l20, y0, cd2));
            const float y3 = fmaf(-l32, y2, fmaf(-l31, y1, fmaf(-l30, y0, cd3)));
            // back substitution
            const float F3 = y3 * i33;
            const float F2 = fmaf(-m23, F3, y2) * i22;
            const float F1 = fmaf(-m13, F3, fmaf(-m12, F2, y1)) * i11;
            const float F0 = fmaf(-m03, F3, fmaf(-m02, F2, fmaf(-m01, F1, y0))) * i00;

            const float2 nF0 = make_float2(-F0, -F0), nF1 = make_float2(-F1, -F1);
            const float2 nF2 = make_float2(-F2, -F2), nF3 = make_float2(-F3, -F3);
            const pf4* r0 = (const pf4*)(bc);
            const pf4* r1 = (const pf4*)(bc + 36);
            const pf4* r2 = (const pf4*)(bc + 72);
            const pf4* r3 = (const pf4*)(bc + 108);
            #pragma unroll
            for (int q = 0; q < 8; q++) {
                const pf4 v0 = r0[q], v1 = r1[q], v2 = r2[q], v3 = r3[q];
                B2[2*q]   = ffma2(nF0, v0.lo, ffma2(nF1, v1.lo,
                            ffma2(nF2, v2.lo, ffma2(nF3, v3.lo, B2[2*q]))));
                B2[2*q+1] = ffma2(nF0, v0.hi, ffma2(nF1, v1.hi,
                            ffma2(nF2, v2.hi, ffma2(nF3, v3.hi, B2[2*q+1]))));
            }
            // block-column fixup: delta - F
            B2[2*kb]   = make_float2(((lane == 4*kb + 0) ? 1.f : 0.f) - F0,
                                     ((lane == 4*kb + 1) ? 1.f : 0.f) - F1);
            B2[2*kb+1] = make_float2(((lane == 4*kb + 2) ? 1.f : 0.f) - F2,
                                     ((lane == 4*kb + 3) ? 1.f : 0.f) - F3);
        }

        // store w*ALPHA*Binv into own sBuf row
        const float sw = w * ALPHA;
        #pragma unroll
        for (int q = 0; q < 8; q++) {
            pf4 v;
            v.lo = make_float2(sw * B2[2*q].x, sw * B2[2*q].y);
            v.hi = make_float2(sw * B2[2*q+1].x, sw * B2[2*q+1].y);
            br[q] = v;
        }
    } else {
        pf4 z; z.lo = make_float2(0.f, 0.f); z.hi = z.lo;
        #pragma unroll
        for (int q = 0; q < 8; q++) br[q] = z;
    }
    __syncthreads();

    // deterministic block reduction over the 8 warps -> partial buffer
    float* outp = g_partial + ((size_t)blockIdx.x * NCN + cn) * 1024;
    for (int e = tid; e < 1024; e += 256) {
        const int r = e >> 5, cc = e & 31;
        float s = 0.f;
        #pragma unroll
        for (int wp = 0; wp < WPB; wp++) s += sBuf[wp][r * 36 + cc];
        outp[e] = s;
    }
}

// ============================================================================
// Mid-reduction: collapse 128 chunks -> 8, at full-chip DRAM bandwidth.
// ============================================================================
__global__ void midreduce_kernel() {
    const int cn = blockIdx.x, g = blockIdx.y, tid = threadIdx.x;
    float s = 0.f;
    const float* pp = g_partial + ((size_t)(g * (NCHUNK / NMID)) * NCN + cn) * 1024 + tid;
    #pragma unroll
    for (int c = 0; c < NCHUNK / NMID; c++) s += pp[(size_t)c * NCN * 1024];
    g_partial2[((size_t)g * NCN + cn) * 1024 + tid] = s;
}

// ============================================================================
// Final kernel: the Cp conjugation collapses polynomially (Cp*Cp = C):
//   out = -Cp*expm(G)*Cp,  G = eta*(Cp*Abar*Cp - ALPHA*I)
//       = -(CF0*C + CF1*(C*Abar*C) + CF2*(C*Abar*C*Abar*C))  + O(||G||^3)
// NO matrix sqrt needed. 3 matmul passes total.
// 256 threads, register-tiled (warp w owns rows 4w..4w+3, lane = column).
// ============================================================================
__device__ __forceinline__ void mm32(const float* __restrict__ A,
                                     const float* __restrict__ B,
                                     float* acc, int r0, int j) {
    #pragma unroll
    for (int kb = 0; kb < 8; kb++) {
        const float4 a0 = *(const float4*)(A + (r0+0)*ST + 4*kb);
        const float4 a1 = *(const float4*)(A + (r0+1)*ST + 4*kb);
        const float4 a2 = *(const float4*)(A + (r0+2)*ST + 4*kb);
        const float4 a3 = *(const float4*)(A + (r0+3)*ST + 4*kb);
        #pragma unroll
        for (int t = 0; t < 4; t++) {
            const float bk = B[(4*kb + t)*ST + j];
            acc[0] = fmaf(f4c(a0, t), bk, acc[0]);
            acc[1] = fmaf(f4c(a1, t), bk, acc[1]);
            acc[2] = fmaf(f4c(a2, t), bk, acc[2]);
            acc[3] = fmaf(f4c(a3, t), bk, acc[3]);
        }
    }
}

__global__ void __launch_bounds__(256) final_kernel(const float* __restrict__ C,
                                                    float* __restrict__ out) {
    __shared__ __align__(16) float sC[32*ST], sA[32*ST];
    __shared__ __align__(16) float sT1[32*ST], sT2[32*ST];
    const int cn = blockIdx.x, tid = threadIdx.x;
    const int warp = tid >> 5, j = tid & 31, r0 = warp << 2;

    // load C and Abar
    #pragma unroll
    for (int r = 0; r < 4; r++) {
        sC[(r0 + r) * ST + j] = C[cn * 1024 + (r0 + r) * 32 + j];
        float s = 0.f;
        #pragma unroll
        for (int g = 0; g < NMID; g++)
            s += g_partial2[((size_t)g * NCN + cn) * 1024 + (r0 + r) * 32 + j];
        sA[(r0 + r) * ST + j] = s * (1.f / 1024.f);
    }
    __syncthreads();

    // T1 = Abar * C
    {
        float acc[4] = {0.f, 0.f, 0.f, 0.f};
        mm32(sA, sC, acc, r0, j);
        #pragma unroll
        for (int r = 0; r < 4; r++) sT1[(r0 + r) * ST + j] = acc[r];
    }
    __syncthreads();
    // T2 = C * T1   (= C*Abar*C)
    {
        float acc[4] = {0.f, 0.f, 0.f, 0.f};
        mm32(sC, sT1, acc, r0, j);
        #pragma unroll
        for (int r = 0; r < 4; r++) sT2[(r0 + r) * ST + j] = acc[r];
    }
    __syncthreads();
    // T3 = T2 * T1  (= C*Abar*C*Abar*C);  out = -(CF0*C + CF1*T2 + CF2*T3)
    {
        float acc[4] = {0.f, 0.f, 0.f, 0.f};
        mm32(sT2, sT1, acc, r0, j);
        #pragma unroll
        for (int r = 0; r < 4; r++) {
            const float o = CF0 * sC[(r0 + r) * ST + j]
                          + CF1 * sT2[(r0 + r) * ST + j]
                          + CF2 * acc[r];
            out[cn * 1024 + (r0 + r) * 32 + j] = -o;
        }
    }
}

// ============================================================================
extern "C" void kernel_launch(void* const* d_in, const int* in_sizes, int n_in,
                              void* d_out, int out_size) {
    const float* X = nullptr;
    const float* C = nullptr;
    const int* idx = nullptr;
    int xElems = 0;
    for (int i = 0; i < n_in; i++) {
        if (in_sizes[i] == NB) idx = (const int*)d_in[i];
        else if (in_sizes[i] == NCN * 1024) C = (const float*)d_in[i];
        else { X = (const float*)d_in[i]; xElems = in_sizes[i]; }
    }
    const int batch = xElems / (NCN * 1024);

    if (batch == NBINS) {
        dedup_kernel<<<1, 1024>>>(idx);
    } else {
        nodedup_kernel<<<1, NB>>>(idx);
    }
    dim3 grid(NCHUNK, NCN);
    main_kernel<<<grid, 256>>>(X, C);
    dim3 mgrid(NCN, NMID);
    midreduce_kernel<<<mgrid, 1024>>>();
    final_kernel<<<NCN, 256>>>(C, (float*)d_out);
}